// round 12
// baseline (speedup 1.0000x reference)
#include <cuda_runtime.h>
#include <math.h>

#define Hh   256
#define Ww   256
#define HWs  65536
#define Bb   4
#define HIDc 100
#define BHW  (Bb*HWs)      /* 262144  */
#define B2HW (Bb*2*HWs)    /* 524288  */

/* d_out flattened tuple offsets: images(6,B,1,H,W), fields(5,B,2,H,W),
   residuals(6,B,1,H,W), grads(6,B,1,2,H,W) */
#define IMG_OFF 0
#define FLD_OFF (6*BHW)              /* 1572864 */
#define RES_OFF (FLD_OFF + 5*B2HW)   /* 4194304 */
#define GRD_OFF (RES_OFF + 6*BHW)    /* 5767168 */

__device__ float g_hA[Bb*HIDc*HWs];
__device__ float g_hB[Bb*HIDc*HWs];
__device__ float g_def[B2HW];
__device__ float g_ft1[B2HW];
__device__ float g_ft2[B2HW];
__device__ float g_rd[2*6*BHW];
__device__ float g_gauss[51];

typedef unsigned long long u64;

/* ---- packed fp32x2 helpers (Blackwell dual fp32 pipe) ---- */
__device__ __forceinline__ void upk2(u64 v, float &lo, float &hi) {
    asm("mov.b64 {%0,%1}, %2;" : "=f"(lo), "=f"(hi) : "l"(v));
}
__device__ __forceinline__ u64 funnel(u64 a, u64 b) {
    /* returns (hi(a), lo(b)) */
    u64 r;
    asm("{\n\t.reg .b32 al, ah, bl, bh;\n\t"
        "mov.b64 {al, ah}, %1;\n\t"
        "mov.b64 {bl, bh}, %2;\n\t"
        "mov.b64 %0, {ah, bl};\n\t}"
        : "=l"(r) : "l"(a), "l"(b));
    return r;
}
__device__ __forceinline__ void ffma2(u64 &d, u64 a, u64 b) {
    asm("fma.rn.f32x2 %0, %1, %2, %0;" : "+l"(d) : "l"(a), "l"(b));
}

/* ---- cp.async helpers ---- */
__device__ __forceinline__ void cp_async16(float* smem_dst, const float* gptr, bool ok) {
    unsigned sa = (unsigned)__cvta_generic_to_shared(smem_dst);
    int sz = ok ? 16 : 0;
    asm volatile("cp.async.cg.shared.global [%0], [%1], 16, %2;"
                 :: "r"(sa), "l"(gptr), "r"(sz));
}
__device__ __forceinline__ void cp_commit() {
    asm volatile("cp.async.commit_group;");
}
__device__ __forceinline__ void cp_wait3() {
    asm volatile("cp.async.wait_group 3;");
}

/* ---------------- small kernels ---------------- */

__global__ void k_gauss() {
    if (threadIdx.x == 0) {
        float v[51]; float s = 0.f;
        for (int t = 0; t < 51; t++) {
            float d = ((float)t - 25.0f) / 10.0f;
            v[t] = expf(-0.5f * d * d);
            s += v[t];
        }
        for (int t = 0; t < 51; t++) g_gauss[t] = v[t] / s;
    }
}

/* fused: deformation init + copy img/res + grad of source */
__global__ void k_init(const float* __restrict__ src,
                       const float* __restrict__ z0,
                       float* __restrict__ out) {
    int gid = blockIdx.x * blockDim.x + threadIdx.x;
    if (gid >= BHW) return;
    int b = gid / HWs, p = gid % HWs;
    int y = p >> 8, x = p & 255;
    g_def[b*2*HWs + p]       = (float)x;
    g_def[b*2*HWs + HWs + p] = (float)y;
    out[IMG_OFF + gid] = src[gid];
    out[RES_OFF + gid] = z0[p];
    const float* im = src + b*HWs;
    int ym = y > 0 ? y-1 : 0, yp = y < 255 ? y+1 : 255;
    int xm = x > 0 ? x-1 : 0, xp = x < 255 ? x+1 : 255;
    float a00 = im[ym*256+xm], a01 = im[ym*256+x], a02 = im[ym*256+xp];
    float a10 = im[y *256+xm],                     a12 = im[y *256+xp];
    float a20 = im[yp*256+xm], a21 = im[yp*256+x], a22 = im[yp*256+xp];
    out[GRD_OFF + b*2*HWs + p]       = ((a02 - a00) + 2.f*(a12 - a10) + (a22 - a20)) * 0.125f;
    out[GRD_OFF + b*2*HWs + HWs + p] = ((a20 - a00) + 2.f*(a21 - a01) + (a22 - a02)) * 0.125f;
}

__global__ void k_grad(const float* __restrict__ img, float* __restrict__ out) {
    int gid = blockIdx.x * blockDim.x + threadIdx.x;
    if (gid >= BHW) return;
    int b = gid / HWs, p = gid % HWs;
    int y = p >> 8, x = p & 255;
    const float* im = img + b*HWs;
    int ym = y > 0 ? y-1 : 0, yp = y < 255 ? y+1 : 255;
    int xm = x > 0 ? x-1 : 0, xp = x < 255 ? x+1 : 255;
    float a00 = im[ym*256+xm], a01 = im[ym*256+x], a02 = im[ym*256+xp];
    float a10 = im[y *256+xm],                     a12 = im[y *256+xp];
    float a20 = im[yp*256+xm], a21 = im[yp*256+x], a22 = im[yp*256+xp];
    float gx = ((a02 - a00) + 2.f*(a12 - a10) + (a22 - a20)) * 0.125f;
    float gy = ((a20 - a00) + 2.f*(a21 - a01) + (a22 - a02)) * 0.125f;
    out[b*2*HWs + p]       = gx;
    out[b*2*HWs + HWs + p] = gy;
}

/* ---------------- conv 3->100, leaky (50 co per block) ---------------- */
__global__ __launch_bounds__(256) void k_conv_c3(
    const float* __restrict__ p0, int s0,
    const float* __restrict__ p1, int s1,
    const float* __restrict__ p2, int s2,
    const float* __restrict__ w, float* __restrict__ out)
{
    __shared__ float ws[1350];
    int tx = threadIdx.x, ty = threadIdx.y;
    int tid = ty*32 + tx;
    int bz = blockIdx.z;
    int b  = bz >> 1;
    int co_base = (bz & 1) * 50;
    for (int idx = tid; idx < 1350; idx += 256) ws[idx] = w[co_base*27 + idx];

    int x0 = blockIdx.x*128 + tx*4;
    int y  = blockIdx.y*8 + ty;
    const float* ch0 = p0 + b*s0;
    const float* ch1 = p1 + b*s1;
    const float* ch2 = p2 + b*s2;

    float v[3][3][6];
#pragma unroll
    for (int ci = 0; ci < 3; ci++) {
        const float* ch = (ci == 0) ? ch0 : (ci == 1 ? ch1 : ch2);
#pragma unroll
        for (int r = 0; r < 3; r++) {
            int yy = y - 1 + r;
            bool yok = (yy >= 0 && yy < 256);
#pragma unroll
            for (int c = 0; c < 6; c++) {
                int xx = x0 - 1 + c;
                v[ci][r][c] = (yok && xx >= 0 && xx < 256) ? ch[yy*256 + xx] : 0.f;
            }
        }
    }
    __syncthreads();

    for (int co = 0; co < 50; co++) {
        float a0 = 0.f, a1 = 0.f, a2 = 0.f, a3 = 0.f;
#pragma unroll
        for (int ci = 0; ci < 3; ci++) {
            const float* wp = &ws[(co*3 + ci)*9];
#pragma unroll
            for (int r = 0; r < 3; r++) {
                float w0 = wp[r*3+0], w1 = wp[r*3+1], w2 = wp[r*3+2];
                a0 += w0*v[ci][r][0] + w1*v[ci][r][1] + w2*v[ci][r][2];
                a1 += w0*v[ci][r][1] + w1*v[ci][r][2] + w2*v[ci][r][3];
                a2 += w0*v[ci][r][2] + w1*v[ci][r][3] + w2*v[ci][r][4];
                a3 += w0*v[ci][r][3] + w1*v[ci][r][4] + w2*v[ci][r][5];
            }
        }
        a0 = a0 >= 0.f ? a0 : 0.01f*a0;
        a1 = a1 >= 0.f ? a1 : 0.01f*a1;
        a2 = a2 >= 0.f ? a2 : 0.01f*a2;
        a3 = a3 >= 0.f ? a3 : 0.01f*a3;
        float4 o = make_float4(a0, a1, a2, a3);
        *(float4*)&out[(b*100 + co_base + co)*HWs + y*256 + x0] = o;
    }
}

/* ---------------- conv 100->X (f32x2, 5-slot ring, hoisted fill) --------- */
/* block (8,16); thread = 8 x-pixels (4 f32x2 pairs) * NCO chans, 1 row.
   Block covers 64x16 px. 5-slot ring of 18x76 planes, prefetch depth 4,
   ci loop = 4 chunks x 5 x 5 (slot index compile-time).
   Fill: 324 vec16 chunks; u=0,1 cover idx 0..255, u=2 covers idx 256..323
   (only tid<68 ISSUES — issuing with sz=0 would zero-fill tile[slot][0],
   racing the real data: that was the R11 corruption bug).
   EPI 0: leaky -> out (B,100,H,W) at co_base        (NCO=4)
   EPI 1: raw   -> out (B,2,H,W)                     (NCO=2)
   EPI 2: res = prev + acc/5 -> out and out2         (NCO=1) */
#define TROW 76
#define TPLANE (18*TROW)       /* 1368 floats */

template<int NCO, int EPI>
__global__ __launch_bounds__(128) void k_conv100(
    const float* __restrict__ in, const float* __restrict__ wbase,
    float* __restrict__ out, const float* __restrict__ prev,
    float* __restrict__ out2, int cgroups)
{
    __shared__ __align__(16) float tile[5][TPLANE];
    __shared__ __align__(16) float wch[NCO*500];   /* 25 ci * 10 pairs * 2 */

    int tx = threadIdx.x, ty = threadIdx.y;
    int tid = ty*8 + tx;
    int bz = blockIdx.z;
    int b = bz / cgroups;
    int co_base = (bz % cgroups) * NCO;

    int gbx = blockIdx.x*64 - 4;
    int gy0 = blockIdx.y*16 - 1;
    const float* inb = in + b*100*HWs;

    /* hoisted fill descriptors: up to 3 chunks per thread, loop-invariant */
    int fsm[3]; const float* fgp[3]; bool fok[3];
    bool act2 = (tid < 68);                 /* u=2 issues only for tid<68 */
#pragma unroll
    for (int u = 0; u < 3; u++) {
        int idx = tid + u*128;
        if (idx < 324) {
            int r = idx / 18, c = idx - r*18;
            int gy = gy0 + r, gxs = gbx + 4*c;
            bool ok = (gy >= 0) & (gy < 256) & (gxs >= 0) & (gxs <= 252);
            fsm[u] = r*TROW + 4*c;
            fgp[u] = ok ? (inb + gy*256 + gxs) : inb;
            fok[u] = ok;
        } else { fsm[u] = 0; fgp[u] = inb; fok[u] = false; }
    }

    u64 acc[NCO][4];
#pragma unroll
    for (int co = 0; co < NCO; co++)
#pragma unroll
        for (int j = 0; j < 4; j++) acc[co][j] = 0ull;

    /* prologue: planes 0..3 -> slots 0..3 */
#pragma unroll
    for (int p = 0; p < 4; p++) {
        cp_async16(&tile[p][fsm[0]], fgp[0], fok[0]);
        cp_async16(&tile[p][fsm[1]], fgp[1], fok[1]);
        if (act2) cp_async16(&tile[p][fsm[2]], fgp[2], fok[2]);
#pragma unroll
        for (int u = 0; u < 3; u++) fgp[u] += HWs;
        cp_commit();
    }

    for (int c4 = 0; c4 < 4; c4++) {
        __syncthreads();   /* all readers done with previous weight chunk */
        /* load weight chunk c4 (25 ci), dup (w,w) pairs, stride 10 pairs */
        for (int idx = tid; idx < NCO*225; idx += 128) {
            int co = idx / 225, rem = idx - co*225;
            int cil = rem / 9, tap = rem - cil*9;
            float w = wbase[(co_base + co)*900 + c4*225 + cil*9 + tap];
            int pos = ((co*25 + cil)*10 + tap)*2;
            wch[pos] = w; wch[pos+1] = w;
        }
        for (int q = 0; q < 5; q++) {
#pragma unroll
            for (int t = 0; t < 5; t++) {
                int ci = c4*25 + q*5 + t;     /* slot = t (compile-time) */
                cp_wait3();
                __syncthreads();
#pragma unroll
                for (int r = 0; r < 3; r++) {
                    const float* rp = &tile[t][(ty + r)*TROW + tx*8];
                    u64 eL = *(const u64*)(rp + 2);
                    float4 q0 = *(const float4*)(rp + 4);
                    float4 q1 = *(const float4*)(rp + 8);
                    u64 e4 = *(const u64*)(rp + 12);
                    u64 e0 = ((const u64*)&q0)[0], e1 = ((const u64*)&q0)[1];
                    u64 e2 = ((const u64*)&q1)[0], e3 = ((const u64*)&q1)[1];
                    u64 o0 = funnel(eL, e0);
                    u64 o1 = funnel(e0, e1);
                    u64 o2 = funnel(e1, e2);
                    u64 o3 = funnel(e2, e3);
                    u64 o4 = funnel(e3, e4);
#pragma unroll
                    for (int co = 0; co < NCO; co++) {
                        const u64* wq = (const u64*)&wch[(co*25 + q*5 + t)*20];
                        u64 w0, w1, w2;
                        if (r == 0) {
                            float4 f = *(const float4*)(wq + 0);
                            w0 = ((const u64*)&f)[0]; w1 = ((const u64*)&f)[1];
                            w2 = wq[2];
                        } else if (r == 1) {
                            w0 = wq[3];
                            float4 f = *(const float4*)(wq + 4);
                            w1 = ((const u64*)&f)[0]; w2 = ((const u64*)&f)[1];
                        } else {
                            float4 f = *(const float4*)(wq + 6);
                            w0 = ((const u64*)&f)[0]; w1 = ((const u64*)&f)[1];
                            w2 = wq[8];
                        }
                        ffma2(acc[co][0], w0, o0);
                        ffma2(acc[co][1], w0, o1);
                        ffma2(acc[co][2], w0, o2);
                        ffma2(acc[co][3], w0, o3);
                        ffma2(acc[co][0], w1, e0);
                        ffma2(acc[co][1], w1, e1);
                        ffma2(acc[co][2], w1, e2);
                        ffma2(acc[co][3], w1, e3);
                        ffma2(acc[co][0], w2, o1);
                        ffma2(acc[co][1], w2, o2);
                        ffma2(acc[co][2], w2, o3);
                        ffma2(acc[co][3], w2, o4);
                    }
                }
                if (ci + 4 < 100) {
                    cp_async16(&tile[(t+4)%5][fsm[0]], fgp[0], fok[0]);
                    cp_async16(&tile[(t+4)%5][fsm[1]], fgp[1], fok[1]);
                    if (act2) cp_async16(&tile[(t+4)%5][fsm[2]], fgp[2], fok[2]);
#pragma unroll
                    for (int u = 0; u < 3; u++) fgp[u] += HWs;
                }
                cp_commit();   /* unconditional: empty groups keep algebra */
            }
        }
    }

    int x0 = blockIdx.x*64 + tx*8;
    int y  = blockIdx.y*16 + ty;
    int pbase = y*256 + x0;

    float a[NCO][8];
#pragma unroll
    for (int co = 0; co < NCO; co++)
#pragma unroll
        for (int j = 0; j < 4; j++) upk2(acc[co][j], a[co][2*j], a[co][2*j+1]);

    if (EPI == 0) {
#pragma unroll
        for (int co = 0; co < NCO; co++) {
#pragma unroll
            for (int px = 0; px < 8; px++) {
                float v = a[co][px];
                a[co][px] = v >= 0.f ? v : 0.01f*v;
            }
            float* dst = out + (b*100 + co_base + co)*HWs + pbase;
            *(float4*)dst     = make_float4(a[co][0],a[co][1],a[co][2],a[co][3]);
            *(float4*)(dst+4) = make_float4(a[co][4],a[co][5],a[co][6],a[co][7]);
        }
    } else if (EPI == 1) {
#pragma unroll
        for (int co = 0; co < NCO; co++) {
            float* dst = out + (b*2 + co_base + co)*HWs + pbase;
            *(float4*)dst     = make_float4(a[co][0],a[co][1],a[co][2],a[co][3]);
            *(float4*)(dst+4) = make_float4(a[co][4],a[co][5],a[co][6],a[co][7]);
        }
    } else {
#pragma unroll
        for (int px = 0; px < 8; px++) {
            float r = prev[b*HWs + pbase + px] + a[0][px] / 5.0f;
            out [b*HWs + pbase + px] = r;
            out2[b*HWs + pbase + px] = r;
        }
    }
}

/* ---------------- blurs ---------------- */

__global__ __launch_bounds__(256) void k_blur_h(const float* __restrict__ in,
                                                float* __restrict__ out) {
    __shared__ float srow[306];
    __shared__ float sg[51];
    int tid = threadIdx.x;
    int rb = blockIdx.x * 256;
    srow[25 + tid] = in[rb + tid];
    if (tid < 25) { srow[tid] = 0.f; srow[281 + tid] = 0.f; }
    if (tid < 51) sg[tid] = g_gauss[tid];
    __syncthreads();
    float acc = 0.f;
#pragma unroll
    for (int k = 0; k < 51; k++) acc += sg[k] * srow[tid + k];
    out[rb + tid] = acc;
}

__global__ __launch_bounds__(256) void k_blur_v(const float* __restrict__ in,
                                                float* __restrict__ fld) {
    __shared__ float sg[51];
    if (threadIdx.x < 51) sg[threadIdx.x] = g_gauss[threadIdx.x];
    __syncthreads();
    int gid = blockIdx.x * 256 + threadIdx.x;
    int x  = gid & 255;
    int y  = (gid >> 8) & 255;
    int ch = gid >> 16;
    const float* col = in + ch*HWs + x;
    float acc = 0.f;
    for (int k = 0; k < 51; k++) {
        int yy = y + k - 25;
        if (yy >= 0 && yy < 256) acc += sg[k] * col[yy*256];
    }
    fld[gid] = acc;
    g_def[gid] -= acc / 5.0f;
}

/* ---------------- deform / compose ---------------- */

__device__ __forceinline__ float bilin(const float* __restrict__ im, float x, float y) {
    float x0f = floorf(x), y0f = floorf(y);
    float wx = x - x0f, wy = y - y0f;
    int x0 = (int)x0f, y0 = (int)y0f;
    float s = 0.f;
#pragma unroll
    for (int dy = 0; dy < 2; dy++) {
        int yi = y0 + dy;
        if (yi < 0 || yi > 255) continue;
        float wyv = dy ? wy : (1.f - wy);
#pragma unroll
        for (int dx = 0; dx < 2; dx++) {
            int xi = x0 + dx;
            if (xi < 0 || xi > 255) continue;
            float wxv = dx ? wx : (1.f - wx);
            s += im[yi*256 + xi] * (wxv * wyv);
        }
    }
    return s;
}

__global__ void k_deform(const float* __restrict__ in, float* __restrict__ out) {
    int gid = blockIdx.x * blockDim.x + threadIdx.x;
    if (gid >= BHW) return;
    int b = gid / HWs, p = gid % HWs;
    float x = g_def[b*2*HWs + p];
    float y = g_def[b*2*HWs + HWs + p];
    out[gid] = bilin(in + b*HWs, x, y);
}

struct Rd5 { const float* p[5]; int n; };

__global__ void k_compose(const float* __restrict__ src,
                          const float* __restrict__ seg,
                          Rd5 rds, float* __restrict__ outimg) {
    int gid = blockIdx.x * blockDim.x + threadIdx.x;
    if (gid >= BHW) return;
    int b = gid / HWs, p = gid % HWs;
    float x = g_def[b*2*HWs + p];
    float y = g_def[b*2*HWs + HWs + p];
    float s = bilin(src + b*HWs, x, y);
    float m = bilin(seg + b*HWs, x, y);
    float acc = rds.p[0][gid];
    for (int j = 1; j < rds.n; j++) acc += rds.p[j][gid];
    outimg[gid] = s + (acc * (float)(0.02*0.02/5.0)) * m;
}

/* ---------------- launch ---------------- */

extern "C" void kernel_launch(void* const* d_in, const int* in_sizes, int n_in,
                              void* d_out, int out_size) {
    const float* src = (const float*)d_in[0];
    const float* seg = (const float*)d_in[1];
    const float* z0  = (const float*)d_in[2];
    const float* zw1 = (const float*)d_in[3];
    const float* zw2 = (const float*)d_in[4];
    const float* zw3 = (const float*)d_in[5];
    const float* vw1 = (const float*)d_in[6];
    const float* vw2 = (const float*)d_in[7];
    const float* vw3 = (const float*)d_in[8];
    float* out = (float*)d_out;

    float *hA, *hB, *defp, *ft1, *ft2, *rd;
    cudaGetSymbolAddress((void**)&hA,  g_hA);
    cudaGetSymbolAddress((void**)&hB,  g_hB);
    cudaGetSymbolAddress((void**)&defp, g_def);
    cudaGetSymbolAddress((void**)&ft1, g_ft1);
    cudaGetSymbolAddress((void**)&ft2, g_ft2);
    cudaGetSymbolAddress((void**)&rd,  g_rd);

    k_gauss<<<1, 32>>>();
    k_init<<<BHW/256, 256>>>(src, z0, out);

    dim3 blk3(32, 8), grd3(2, 32, Bb*2);
    dim3 blkC(8, 16);

    for (int i = 0; i < 5; i++) {
        /* ---- z path: residual update ---- */
        k_conv_c3<<<grd3, blk3>>>(out + RES_OFF + i*BHW, HWs,
                                  out + IMG_OFF + i*BHW, HWs,
                                  out + IMG_OFF,         HWs,
                                  zw1 + i*2700, hA);
        k_conv100<4,0><<<dim3(4,16,Bb*25), blkC>>>(hA, zw2 + i*90000, hB,
                                                   nullptr, nullptr, 25);
        float* rd_new = rd + (((size_t)(i % 2))*6 + (i + 1))*BHW;
        k_conv100<1,2><<<dim3(4,16,Bb), blkC>>>(hB, zw3 + i*900,
                                                out + RES_OFF + (i+1)*BHW,
                                                out + RES_OFF + i*BHW,
                                                rd_new, 1);
        /* ---- re-deform previous residuals with PRE-update deformation ---- */
        for (int j = 1; j <= i; j++) {
            const float* s_ = rd + (((size_t)((i+1) % 2))*6 + j)*BHW;
            float*       d_ = rd + (((size_t)(i % 2))*6 + j)*BHW;
            k_deform<<<BHW/256, 256>>>(s_, d_);
        }
        /* ---- v path: velocity field ---- */
        k_conv_c3<<<grd3, blk3>>>(defp,       2*HWs,
                                  defp + HWs, 2*HWs,
                                  out + IMG_OFF + i*BHW, HWs,
                                  vw1 + i*2700, hA);
        k_conv100<4,0><<<dim3(4,16,Bb*25), blkC>>>(hA, vw2 + i*90000, hB,
                                                   nullptr, nullptr, 25);
        k_conv100<2,1><<<dim3(4,16,Bb), blkC>>>(hB, vw3 + i*1800, ft1,
                                                nullptr, nullptr, 1);
        k_blur_h<<<Bb*2*Hh, 256>>>(ft1, ft2);
        k_blur_v<<<B2HW/256, 256>>>(ft2, out + FLD_OFF + i*B2HW);  /* also updates g_def */

        /* ---- compose new image with POST-update deformation ---- */
        Rd5 rds;
        rds.n = i + 1;
        for (int j = 0; j < 5; j++) {
            int slot = (j <= i) ? (j + 1) : 1;
            rds.p[j] = rd + (((size_t)(i % 2))*6 + slot)*BHW;
        }
        k_compose<<<BHW/256, 256>>>(out + IMG_OFF, seg, rds,
                                    out + IMG_OFF + (i+1)*BHW);
        k_grad<<<BHW/256, 256>>>(out + IMG_OFF + (i+1)*BHW,
                                 out + GRD_OFF + (i+1)*B2HW);
    }
}

// round 16
// speedup vs baseline: 1.3264x; 1.3264x over previous
#include <cuda_runtime.h>
#include <math.h>

#define Hh   256
#define Ww   256
#define HWs  65536
#define Bb   4
#define HIDc 100
#define BHW  (Bb*HWs)      /* 262144  */
#define B2HW (Bb*2*HWs)    /* 524288  */

/* d_out flattened tuple offsets: images(6,B,1,H,W), fields(5,B,2,H,W),
   residuals(6,B,1,H,W), grads(6,B,1,2,H,W) */
#define IMG_OFF 0
#define FLD_OFF (6*BHW)              /* 1572864 */
#define RES_OFF (FLD_OFF + 5*B2HW)   /* 4194304 */
#define GRD_OFF (RES_OFF + 6*BHW)    /* 5767168 */

__device__ float g_hA[Bb*HIDc*HWs];
__device__ float g_hB[Bb*HIDc*HWs];
__device__ float g_def[B2HW];
__device__ float g_ft2[B2HW];
__device__ float g_fp[2*B2HW];   /* field conv partials (ci split) */
__device__ float g_rp[2*BHW];    /* residual conv partials (ci split) */
__device__ float g_rd[2*6*BHW];
__device__ float g_gauss[51];

typedef unsigned long long u64;

/* ---- packed fp32x2 helpers (Blackwell dual fp32 pipe) ---- */
__device__ __forceinline__ void upk2(u64 v, float &lo, float &hi) {
    asm("mov.b64 {%0,%1}, %2;" : "=f"(lo), "=f"(hi) : "l"(v));
}
__device__ __forceinline__ u64 funnel(u64 a, u64 b) {
    /* returns (hi(a), lo(b)) */
    u64 r;
    asm("{\n\t.reg .b32 al, ah, bl, bh;\n\t"
        "mov.b64 {al, ah}, %1;\n\t"
        "mov.b64 {bl, bh}, %2;\n\t"
        "mov.b64 %0, {ah, bl};\n\t}"
        : "=l"(r) : "l"(a), "l"(b));
    return r;
}
__device__ __forceinline__ void ffma2(u64 &d, u64 a, u64 b) {
    asm("fma.rn.f32x2 %0, %1, %2, %0;" : "+l"(d) : "l"(a), "l"(b));
}

/* ---- cp.async helpers ---- */
__device__ __forceinline__ void cp_async16(float* smem_dst, const float* gptr, bool ok) {
    unsigned sa = (unsigned)__cvta_generic_to_shared(smem_dst);
    int sz = ok ? 16 : 0;
    asm volatile("cp.async.cg.shared.global [%0], [%1], 16, %2;"
                 :: "r"(sa), "l"(gptr), "r"(sz));
}
__device__ __forceinline__ void cp_commit() {
    asm volatile("cp.async.commit_group;");
}
__device__ __forceinline__ void cp_wait1() {
    asm volatile("cp.async.wait_group 1;");
}

/* ---------------- small kernels ---------------- */

__global__ void k_gauss() {
    if (threadIdx.x == 0) {
        float v[51]; float s = 0.f;
        for (int t = 0; t < 51; t++) {
            float d = ((float)t - 25.0f) / 10.0f;
            v[t] = expf(-0.5f * d * d);
            s += v[t];
        }
        for (int t = 0; t < 51; t++) g_gauss[t] = v[t] / s;
    }
}

/* fused: deformation init + copy img/res + grad of source */
__global__ void k_init(const float* __restrict__ src,
                       const float* __restrict__ z0,
                       float* __restrict__ out) {
    int gid = blockIdx.x * blockDim.x + threadIdx.x;
    if (gid >= BHW) return;
    int b = gid / HWs, p = gid % HWs;
    int y = p >> 8, x = p & 255;
    g_def[b*2*HWs + p]       = (float)x;
    g_def[b*2*HWs + HWs + p] = (float)y;
    out[IMG_OFF + gid] = src[gid];
    out[RES_OFF + gid] = z0[p];
    const float* im = src + b*HWs;
    int ym = y > 0 ? y-1 : 0, yp = y < 255 ? y+1 : 255;
    int xm = x > 0 ? x-1 : 0, xp = x < 255 ? x+1 : 255;
    float a00 = im[ym*256+xm], a01 = im[ym*256+x], a02 = im[ym*256+xp];
    float a10 = im[y *256+xm],                     a12 = im[y *256+xp];
    float a20 = im[yp*256+xm], a21 = im[yp*256+x], a22 = im[yp*256+xp];
    out[GRD_OFF + b*2*HWs + p]       = ((a02 - a00) + 2.f*(a12 - a10) + (a22 - a20)) * 0.125f;
    out[GRD_OFF + b*2*HWs + HWs + p] = ((a20 - a00) + 2.f*(a21 - a01) + (a22 - a02)) * 0.125f;
}

__global__ void k_grad(const float* __restrict__ img, float* __restrict__ out) {
    int gid = blockIdx.x * blockDim.x + threadIdx.x;
    if (gid >= BHW) return;
    int b = gid / HWs, p = gid % HWs;
    int y = p >> 8, x = p & 255;
    const float* im = img + b*HWs;
    int ym = y > 0 ? y-1 : 0, yp = y < 255 ? y+1 : 255;
    int xm = x > 0 ? x-1 : 0, xp = x < 255 ? x+1 : 255;
    float a00 = im[ym*256+xm], a01 = im[ym*256+x], a02 = im[ym*256+xp];
    float a10 = im[y *256+xm],                     a12 = im[y *256+xp];
    float a20 = im[yp*256+xm], a21 = im[yp*256+x], a22 = im[yp*256+xp];
    float gx = ((a02 - a00) + 2.f*(a12 - a10) + (a22 - a20)) * 0.125f;
    float gy = ((a20 - a00) + 2.f*(a21 - a01) + (a22 - a02)) * 0.125f;
    out[b*2*HWs + p]       = gx;
    out[b*2*HWs + HWs + p] = gy;
}

/* residual combine: res = prev + (pA + pB)/5 -> out_res and rd_new */
__global__ void k_res_combine(const float* __restrict__ prev,
                              const float* __restrict__ parts,
                              float* __restrict__ out_res,
                              float* __restrict__ rd_new) {
    int gid = blockIdx.x * blockDim.x + threadIdx.x;
    if (gid >= BHW) return;
    float r = prev[gid] + (parts[gid] + parts[gid + BHW]) / 5.0f;
    out_res[gid] = r;
    rd_new[gid]  = r;
}

/* ---------------- conv 3->100, leaky (50 co per block) ---------------- */
__global__ __launch_bounds__(256) void k_conv_c3(
    const float* __restrict__ p0, int s0,
    const float* __restrict__ p1, int s1,
    const float* __restrict__ p2, int s2,
    const float* __restrict__ w, float* __restrict__ out)
{
    __shared__ float ws[1350];
    int tx = threadIdx.x, ty = threadIdx.y;
    int tid = ty*32 + tx;
    int bz = blockIdx.z;
    int b  = bz >> 1;
    int co_base = (bz & 1) * 50;
    for (int idx = tid; idx < 1350; idx += 256) ws[idx] = w[co_base*27 + idx];

    int x0 = blockIdx.x*128 + tx*4;
    int y  = blockIdx.y*8 + ty;
    const float* ch0 = p0 + b*s0;
    const float* ch1 = p1 + b*s1;
    const float* ch2 = p2 + b*s2;

    float v[3][3][6];
#pragma unroll
    for (int ci = 0; ci < 3; ci++) {
        const float* ch = (ci == 0) ? ch0 : (ci == 1 ? ch1 : ch2);
#pragma unroll
        for (int r = 0; r < 3; r++) {
            int yy = y - 1 + r;
            bool yok = (yy >= 0 && yy < 256);
#pragma unroll
            for (int c = 0; c < 6; c++) {
                int xx = x0 - 1 + c;
                v[ci][r][c] = (yok && xx >= 0 && xx < 256) ? ch[yy*256 + xx] : 0.f;
            }
        }
    }
    __syncthreads();

    for (int co = 0; co < 50; co++) {
        float a0 = 0.f, a1 = 0.f, a2 = 0.f, a3 = 0.f;
#pragma unroll
        for (int ci = 0; ci < 3; ci++) {
            const float* wp = &ws[(co*3 + ci)*9];
#pragma unroll
            for (int r = 0; r < 3; r++) {
                float w0 = wp[r*3+0], w1 = wp[r*3+1], w2 = wp[r*3+2];
                a0 += w0*v[ci][r][0] + w1*v[ci][r][1] + w2*v[ci][r][2];
                a1 += w0*v[ci][r][1] + w1*v[ci][r][2] + w2*v[ci][r][3];
                a2 += w0*v[ci][r][2] + w1*v[ci][r][3] + w2*v[ci][r][4];
                a3 += w0*v[ci][r][3] + w1*v[ci][r][4] + w2*v[ci][r][5];
            }
        }
        a0 = a0 >= 0.f ? a0 : 0.01f*a0;
        a1 = a1 >= 0.f ? a1 : 0.01f*a1;
        a2 = a2 >= 0.f ? a2 : 0.01f*a2;
        a3 = a3 >= 0.f ? a3 : 0.01f*a3;
        float4 o = make_float4(a0, a1, a2, a3);
        *(float4*)&out[(b*100 + co_base + co)*HWs + y*256 + x0] = o;
    }
}

/* ---------------- conv 100->X (f32x2, 3-slot ring, chunked weights) ------ */
/* block (8,16); thread = 8 x-pixels (4 f32x2 pairs) * NCO chans, 1 row.
   Block covers 64x16 px. 3-slot ring of 18x76 planes (runtime slot idx),
   prefetch depth 2, weights chunked 25 ci at a time.
   NS = ci split factor (1 = full 100; 2 = this block does 50 ci starting
   at s*50, where grid.z encodes (b, s, co-group)).
   EPI 0: leaky -> out (B,100,H,W) at co_base        (NCO=5, NS=1)
   EPI 1: raw partial -> out + ((s*Bb+b)*2+co)*HWs   (NCO=2, NS=2)
   EPI 3: raw partial -> out + (s*Bb+b)*HWs          (NCO=1, NS=2) */
#define TROW 76
#define TPLANE (18*TROW)       /* 1368 floats */

template<int NCO, int EPI, int NS>
__global__ __launch_bounds__(128) void k_conv100(
    const float* __restrict__ in, const float* __restrict__ wbase,
    float* __restrict__ out, int cgroups)
{
    __shared__ __align__(16) float tile[3][TPLANE];
    __shared__ __align__(16) float wch[NCO*500];   /* 25 ci * 10 pairs * 2 */

    int tx = threadIdx.x, ty = threadIdx.y;
    int tid = ty*8 + tx;
    int bz = blockIdx.z;
    int g = bz % cgroups;
    int rest = bz / cgroups;
    int s = rest % NS;
    int b = rest / NS;
    int co_base = g * NCO;

    const int cilen = 100 / NS;
    const int cb = s * cilen;

    int gbx = blockIdx.x*64 - 4;
    int gy0 = blockIdx.y*16 - 1;
    const float* inb = in + b*100*HWs;

    /* load one 25-ci weight chunk (absolute chunk index ca) */
    auto wfill = [&](int ca) {
        for (int idx = tid; idx < NCO*225; idx += 128) {
            int co = idx / 225, rem = idx - co*225;
            int cil = rem / 9, tap = rem - cil*9;
            float w = wbase[(co_base + co)*900 + (ca*25 + cil)*9 + tap];
            int pos = ((co*25 + cil)*10 + tap)*2;
            wch[pos] = w; wch[pos+1] = w;
        }
    };

    /* async vec16 fill of one ci plane: 18 rows x 18 chunks = 324 */
    auto fill = [&](int slot, int ci) {
        float* dst = &tile[slot][0];
        const float* srcp = inb + ci*HWs;
#pragma unroll
        for (int u = 0; u < 3; u++) {
            int idx = tid + u*128;
            if (idx < 324) {
                int r = idx / 18, c = idx - r*18;
                int gy = gy0 + r;
                int gxs = gbx + 4*c;
                bool ok = (gy >= 0) & (gy < 256) & (gxs >= 0) & (gxs <= 252);
                const float* gp = ok ? (srcp + gy*256 + gxs) : srcp;
                cp_async16(dst + r*TROW + 4*c, gp, ok);
            }
        }
    };

    u64 acc[NCO][4];
#pragma unroll
    for (int co = 0; co < NCO; co++)
#pragma unroll
        for (int j = 0; j < 4; j++) acc[co][j] = 0ull;

    wfill(cb / 25);
    fill(0, cb);     cp_commit();
    fill(1, cb + 1); cp_commit();

    int slot = 0, cil = 0;
    for (int ci = cb; ci < cb + cilen; ci++) {
        cp_wait1();
        __syncthreads();

        if (cil == 25) {
            wfill(ci / 25);
            __syncthreads();
            cil = 0;
        }

#pragma unroll
        for (int r = 0; r < 3; r++) {
            const float* rp = &tile[slot][(ty + r)*TROW + tx*8];
            u64 eL = *(const u64*)(rp + 2);
            float4 q0 = *(const float4*)(rp + 4);
            float4 q1 = *(const float4*)(rp + 8);
            u64 e4 = *(const u64*)(rp + 12);
            u64 e0 = ((const u64*)&q0)[0], e1 = ((const u64*)&q0)[1];
            u64 e2 = ((const u64*)&q1)[0], e3 = ((const u64*)&q1)[1];
            u64 o0 = funnel(eL, e0);
            u64 o1 = funnel(e0, e1);
            u64 o2 = funnel(e1, e2);
            u64 o3 = funnel(e2, e3);
            u64 o4 = funnel(e3, e4);
#pragma unroll
            for (int co = 0; co < NCO; co++) {
                const u64* wq = (const u64*)&wch[(co*25 + cil)*20];
                u64 w0, w1, w2;
                if (r == 0) {
                    float4 f = *(const float4*)(wq + 0);
                    w0 = ((const u64*)&f)[0]; w1 = ((const u64*)&f)[1];
                    w2 = wq[2];
                } else if (r == 1) {
                    w0 = wq[3];
                    float4 f = *(const float4*)(wq + 4);
                    w1 = ((const u64*)&f)[0]; w2 = ((const u64*)&f)[1];
                } else {
                    float4 f = *(const float4*)(wq + 6);
                    w0 = ((const u64*)&f)[0]; w1 = ((const u64*)&f)[1];
                    w2 = wq[8];
                }
                ffma2(acc[co][0], w0, o0);
                ffma2(acc[co][1], w0, o1);
                ffma2(acc[co][2], w0, o2);
                ffma2(acc[co][3], w0, o3);
                ffma2(acc[co][0], w1, e0);
                ffma2(acc[co][1], w1, e1);
                ffma2(acc[co][2], w1, e2);
                ffma2(acc[co][3], w1, e3);
                ffma2(acc[co][0], w2, o1);
                ffma2(acc[co][1], w2, o2);
                ffma2(acc[co][2], w2, o3);
                ffma2(acc[co][3], w2, o4);
            }
        }

        if (ci + 2 < cb + cilen) fill(slot == 2 ? 1 : (slot == 1 ? 0 : 2), ci + 2);
        cp_commit();
        slot = (slot == 2) ? 0 : slot + 1;
        cil++;
    }

    int x0 = blockIdx.x*64 + tx*8;
    int y  = blockIdx.y*16 + ty;
    int pbase = y*256 + x0;

    float a[NCO][8];
#pragma unroll
    for (int co = 0; co < NCO; co++)
#pragma unroll
        for (int j = 0; j < 4; j++) upk2(acc[co][j], a[co][2*j], a[co][2*j+1]);

    if (EPI == 0) {
#pragma unroll
        for (int co = 0; co < NCO; co++) {
#pragma unroll
            for (int px = 0; px < 8; px++) {
                float v = a[co][px];
                a[co][px] = v >= 0.f ? v : 0.01f*v;
            }
            float* dst = out + (b*100 + co_base + co)*HWs + pbase;
            *(float4*)dst     = make_float4(a[co][0],a[co][1],a[co][2],a[co][3]);
            *(float4*)(dst+4) = make_float4(a[co][4],a[co][5],a[co][6],a[co][7]);
        }
    } else if (EPI == 1) {
#pragma unroll
        for (int co = 0; co < NCO; co++) {
            float* dst = out + ((s*Bb + b)*2 + co)*HWs + pbase;
            *(float4*)dst     = make_float4(a[co][0],a[co][1],a[co][2],a[co][3]);
            *(float4*)(dst+4) = make_float4(a[co][4],a[co][5],a[co][6],a[co][7]);
        }
    } else {
        float* dst = out + (s*Bb + b)*HWs + pbase;
        *(float4*)dst     = make_float4(a[0][0],a[0][1],a[0][2],a[0][3]);
        *(float4*)(dst+4) = make_float4(a[0][4],a[0][5],a[0][6],a[0][7]);
    }
}

/* ---------------- blurs ---------------- */

/* reads summed ci-split partials: in[gid] + in[gid + B2HW] */
__global__ __launch_bounds__(256) void k_blur_h(const float* __restrict__ in,
                                                float* __restrict__ out) {
    __shared__ float srow[306];
    __shared__ float sg[51];
    int tid = threadIdx.x;
    int rb = blockIdx.x * 256;
    srow[25 + tid] = in[rb + tid] + in[rb + tid + B2HW];
    if (tid < 25) { srow[tid] = 0.f; srow[281 + tid] = 0.f; }
    if (tid < 51) sg[tid] = g_gauss[tid];
    __syncthreads();
    float acc = 0.f;
#pragma unroll
    for (int k = 0; k < 51; k++) acc += sg[k] * srow[tid + k];
    out[rb + tid] = acc;
}

__global__ __launch_bounds__(256) void k_blur_v(const float* __restrict__ in,
                                                float* __restrict__ fld) {
    __shared__ float sg[51];
    if (threadIdx.x < 51) sg[threadIdx.x] = g_gauss[threadIdx.x];
    __syncthreads();
    int gid = blockIdx.x * 256 + threadIdx.x;
    int x  = gid & 255;
    int y  = (gid >> 8) & 255;
    int ch = gid >> 16;
    const float* col = in + ch*HWs + x;
    float acc = 0.f;
    for (int k = 0; k < 51; k++) {
        int yy = y + k - 25;
        if (yy >= 0 && yy < 256) acc += sg[k] * col[yy*256];
    }
    fld[gid] = acc;
    g_def[gid] -= acc / 5.0f;
}

/* ---------------- deform / compose ---------------- */

__device__ __forceinline__ float bilin(const float* __restrict__ im, float x, float y) {
    float x0f = floorf(x), y0f = floorf(y);
    float wx = x - x0f, wy = y - y0f;
    int x0 = (int)x0f, y0 = (int)y0f;
    float s = 0.f;
#pragma unroll
    for (int dy = 0; dy < 2; dy++) {
        int yi = y0 + dy;
        if (yi < 0 || yi > 255) continue;
        float wyv = dy ? wy : (1.f - wy);
#pragma unroll
        for (int dx = 0; dx < 2; dx++) {
            int xi = x0 + dx;
            if (xi < 0 || xi > 255) continue;
            float wxv = dx ? wx : (1.f - wx);
            s += im[yi*256 + xi] * (wxv * wyv);
        }
    }
    return s;
}

__global__ void k_deform(const float* __restrict__ in, float* __restrict__ out) {
    int gid = blockIdx.x * blockDim.x + threadIdx.x;
    if (gid >= BHW) return;
    int b = gid / HWs, p = gid % HWs;
    float x = g_def[b*2*HWs + p];
    float y = g_def[b*2*HWs + HWs + p];
    out[gid] = bilin(in + b*HWs, x, y);
}

struct Rd5 { const float* p[5]; int n; };

__global__ void k_compose(const float* __restrict__ src,
                          const float* __restrict__ seg,
                          Rd5 rds, float* __restrict__ outimg) {
    int gid = blockIdx.x * blockDim.x + threadIdx.x;
    if (gid >= BHW) return;
    int b = gid / HWs, p = gid % HWs;
    float x = g_def[b*2*HWs + p];
    float y = g_def[b*2*HWs + HWs + p];
    float s = bilin(src + b*HWs, x, y);
    float m = bilin(seg + b*HWs, x, y);
    float acc = rds.p[0][gid];
    for (int j = 1; j < rds.n; j++) acc += rds.p[j][gid];
    outimg[gid] = s + (acc * (float)(0.02*0.02/5.0)) * m;
}

/* ---------------- launch ---------------- */

extern "C" void kernel_launch(void* const* d_in, const int* in_sizes, int n_in,
                              void* d_out, int out_size) {
    const float* src = (const float*)d_in[0];
    const float* seg = (const float*)d_in[1];
    const float* z0  = (const float*)d_in[2];
    const float* zw1 = (const float*)d_in[3];
    const float* zw2 = (const float*)d_in[4];
    const float* zw3 = (const float*)d_in[5];
    const float* vw1 = (const float*)d_in[6];
    const float* vw2 = (const float*)d_in[7];
    const float* vw3 = (const float*)d_in[8];
    float* out = (float*)d_out;

    float *hA, *hB, *defp, *ft2, *fp, *rp, *rd;
    cudaGetSymbolAddress((void**)&hA,  g_hA);
    cudaGetSymbolAddress((void**)&hB,  g_hB);
    cudaGetSymbolAddress((void**)&defp, g_def);
    cudaGetSymbolAddress((void**)&ft2, g_ft2);
    cudaGetSymbolAddress((void**)&fp,  g_fp);
    cudaGetSymbolAddress((void**)&rp,  g_rp);
    cudaGetSymbolAddress((void**)&rd,  g_rd);

    k_gauss<<<1, 32>>>();
    k_init<<<BHW/256, 256>>>(src, z0, out);

    dim3 blk3(32, 8), grd3(2, 32, Bb*2);
    dim3 blkC(8, 16);

    for (int i = 0; i < 5; i++) {
        /* ---- z path: residual update ---- */
        k_conv_c3<<<grd3, blk3>>>(out + RES_OFF + i*BHW, HWs,
                                  out + IMG_OFF + i*BHW, HWs,
                                  out + IMG_OFF,         HWs,
                                  zw1 + i*2700, hA);
        k_conv100<5,0,1><<<dim3(4,16,Bb*20), blkC>>>(hA, zw2 + i*90000, hB, 20);
        /* 100->1 conv split over ci halves -> partials, then combine */
        k_conv100<1,3,2><<<dim3(4,16,Bb*2), blkC>>>(hB, zw3 + i*900, rp, 1);
        float* rd_new = rd + (((size_t)(i % 2))*6 + (i + 1))*BHW;
        k_res_combine<<<BHW/256, 256>>>(out + RES_OFF + i*BHW, rp,
                                        out + RES_OFF + (i+1)*BHW, rd_new);
        /* ---- re-deform previous residuals with PRE-update deformation ---- */
        for (int j = 1; j <= i; j++) {
            const float* s_ = rd + (((size_t)((i+1) % 2))*6 + j)*BHW;
            float*       d_ = rd + (((size_t)(i % 2))*6 + j)*BHW;
            k_deform<<<BHW/256, 256>>>(s_, d_);
        }
        /* ---- v path: velocity field ---- */
        k_conv_c3<<<grd3, blk3>>>(defp,       2*HWs,
                                  defp + HWs, 2*HWs,
                                  out + IMG_OFF + i*BHW, HWs,
                                  vw1 + i*2700, hA);
        k_conv100<5,0,1><<<dim3(4,16,Bb*20), blkC>>>(hA, vw2 + i*90000, hB, 20);
        /* 100->2 conv split over ci halves -> partials; blur_h sums them */
        k_conv100<2,1,2><<<dim3(4,16,Bb*2), blkC>>>(hB, vw3 + i*1800, fp, 1);
        k_blur_h<<<Bb*2*Hh, 256>>>(fp, ft2);
        k_blur_v<<<B2HW/256, 256>>>(ft2, out + FLD_OFF + i*B2HW);  /* also updates g_def */

        /* ---- compose new image with POST-update deformation ---- */
        Rd5 rds;
        rds.n = i + 1;
        for (int j = 0; j < 5; j++) {
            int slot = (j <= i) ? (j + 1) : 1;
            rds.p[j] = rd + (((size_t)(i % 2))*6 + slot)*BHW;
        }
        k_compose<<<BHW/256, 256>>>(out + IMG_OFF, seg, rds,
                                    out + IMG_OFF + (i+1)*BHW);
        k_grad<<<BHW/256, 256>>>(out + IMG_OFF + (i+1)*BHW,
                                 out + GRD_OFF + (i+1)*B2HW);
    }
}

// round 17
// speedup vs baseline: 1.4963x; 1.1281x over previous
#include <cuda_runtime.h>
#include <math.h>

#define Hh   256
#define Ww   256
#define HWs  65536
#define Bb   4
#define HIDc 100
#define BHW  (Bb*HWs)      /* 262144  */
#define B2HW (Bb*2*HWs)    /* 524288  */

/* d_out flattened tuple offsets: images(6,B,1,H,W), fields(5,B,2,H,W),
   residuals(6,B,1,H,W), grads(6,B,1,2,H,W) */
#define IMG_OFF 0
#define FLD_OFF (6*BHW)              /* 1572864 */
#define RES_OFF (FLD_OFF + 5*B2HW)   /* 4194304 */
#define GRD_OFF (RES_OFF + 6*BHW)    /* 5767168 */

__device__ float g_hA[Bb*HIDc*HWs];
__device__ float g_hB[Bb*HIDc*HWs];
__device__ float g_def[B2HW];
__device__ float g_ft2[B2HW];
__device__ float g_fp[2*B2HW];   /* field conv partials (ci split) */
__device__ float g_rp[2*BHW];    /* residual conv partials (ci split) */
__device__ float g_rd[2*6*BHW];
__device__ float g_gauss[51];

typedef unsigned long long u64;

/* ---- packed fp32x2 helpers (Blackwell dual fp32 pipe) ---- */
__device__ __forceinline__ void upk2(u64 v, float &lo, float &hi) {
    asm("mov.b64 {%0,%1}, %2;" : "=f"(lo), "=f"(hi) : "l"(v));
}
__device__ __forceinline__ u64 funnel(u64 a, u64 b) {
    /* returns (hi(a), lo(b)) */
    u64 r;
    asm("{\n\t.reg .b32 al, ah, bl, bh;\n\t"
        "mov.b64 {al, ah}, %1;\n\t"
        "mov.b64 {bl, bh}, %2;\n\t"
        "mov.b64 %0, {ah, bl};\n\t}"
        : "=l"(r) : "l"(a), "l"(b));
    return r;
}
__device__ __forceinline__ void ffma2(u64 &d, u64 a, u64 b) {
    asm("fma.rn.f32x2 %0, %1, %2, %0;" : "+l"(d) : "l"(a), "l"(b));
}

/* ---- cp.async helpers ---- */
__device__ __forceinline__ void cp_async16(float* smem_dst, const float* gptr, bool ok) {
    unsigned sa = (unsigned)__cvta_generic_to_shared(smem_dst);
    int sz = ok ? 16 : 0;
    asm volatile("cp.async.cg.shared.global [%0], [%1], 16, %2;"
                 :: "r"(sa), "l"(gptr), "r"(sz));
}
__device__ __forceinline__ void cp_commit() {
    asm volatile("cp.async.commit_group;");
}
__device__ __forceinline__ void cp_wait0() {
    asm volatile("cp.async.wait_group 0;");
}

/* ---------------- small kernels ---------------- */

__global__ void k_gauss() {
    if (threadIdx.x == 0) {
        float v[51]; float s = 0.f;
        for (int t = 0; t < 51; t++) {
            float d = ((float)t - 25.0f) / 10.0f;
            v[t] = expf(-0.5f * d * d);
            s += v[t];
        }
        for (int t = 0; t < 51; t++) g_gauss[t] = v[t] / s;
    }
}

/* fused: deformation init + copy img/res + grad of source */
__global__ void k_init(const float* __restrict__ src,
                       const float* __restrict__ z0,
                       float* __restrict__ out) {
    int gid = blockIdx.x * blockDim.x + threadIdx.x;
    if (gid >= BHW) return;
    int b = gid / HWs, p = gid % HWs;
    int y = p >> 8, x = p & 255;
    g_def[b*2*HWs + p]       = (float)x;
    g_def[b*2*HWs + HWs + p] = (float)y;
    out[IMG_OFF + gid] = src[gid];
    out[RES_OFF + gid] = z0[p];
    const float* im = src + b*HWs;
    int ym = y > 0 ? y-1 : 0, yp = y < 255 ? y+1 : 255;
    int xm = x > 0 ? x-1 : 0, xp = x < 255 ? x+1 : 255;
    float a00 = im[ym*256+xm], a01 = im[ym*256+x], a02 = im[ym*256+xp];
    float a10 = im[y *256+xm],                     a12 = im[y *256+xp];
    float a20 = im[yp*256+xm], a21 = im[yp*256+x], a22 = im[yp*256+xp];
    out[GRD_OFF + b*2*HWs + p]       = ((a02 - a00) + 2.f*(a12 - a10) + (a22 - a20)) * 0.125f;
    out[GRD_OFF + b*2*HWs + HWs + p] = ((a20 - a00) + 2.f*(a21 - a01) + (a22 - a02)) * 0.125f;
}

__global__ void k_grad(const float* __restrict__ img, float* __restrict__ out) {
    int gid = blockIdx.x * blockDim.x + threadIdx.x;
    if (gid >= BHW) return;
    int b = gid / HWs, p = gid % HWs;
    int y = p >> 8, x = p & 255;
    const float* im = img + b*HWs;
    int ym = y > 0 ? y-1 : 0, yp = y < 255 ? y+1 : 255;
    int xm = x > 0 ? x-1 : 0, xp = x < 255 ? x+1 : 255;
    float a00 = im[ym*256+xm], a01 = im[ym*256+x], a02 = im[ym*256+xp];
    float a10 = im[y *256+xm],                     a12 = im[y *256+xp];
    float a20 = im[yp*256+xm], a21 = im[yp*256+x], a22 = im[yp*256+xp];
    float gx = ((a02 - a00) + 2.f*(a12 - a10) + (a22 - a20)) * 0.125f;
    float gy = ((a20 - a00) + 2.f*(a21 - a01) + (a22 - a02)) * 0.125f;
    out[b*2*HWs + p]       = gx;
    out[b*2*HWs + HWs + p] = gy;
}

/* residual combine: res = prev + (pA + pB)/5 -> out_res and rd_new */
__global__ void k_res_combine(const float* __restrict__ prev,
                              const float* __restrict__ parts,
                              float* __restrict__ out_res,
                              float* __restrict__ rd_new) {
    int gid = blockIdx.x * blockDim.x + threadIdx.x;
    if (gid >= BHW) return;
    float r = prev[gid] + (parts[gid] + parts[gid + BHW]) / 5.0f;
    out_res[gid] = r;
    rd_new[gid]  = r;
}

/* ---------------- conv 3->100, leaky (50 co per block) ---------------- */
__global__ __launch_bounds__(256) void k_conv_c3(
    const float* __restrict__ p0, int s0,
    const float* __restrict__ p1, int s1,
    const float* __restrict__ p2, int s2,
    const float* __restrict__ w, float* __restrict__ out)
{
    __shared__ float ws[1350];
    int tx = threadIdx.x, ty = threadIdx.y;
    int tid = ty*32 + tx;
    int bz = blockIdx.z;
    int b  = bz >> 1;
    int co_base = (bz & 1) * 50;
    for (int idx = tid; idx < 1350; idx += 256) ws[idx] = w[co_base*27 + idx];

    int x0 = blockIdx.x*128 + tx*4;
    int y  = blockIdx.y*8 + ty;
    const float* ch0 = p0 + b*s0;
    const float* ch1 = p1 + b*s1;
    const float* ch2 = p2 + b*s2;

    float v[3][3][6];
#pragma unroll
    for (int ci = 0; ci < 3; ci++) {
        const float* ch = (ci == 0) ? ch0 : (ci == 1 ? ch1 : ch2);
#pragma unroll
        for (int r = 0; r < 3; r++) {
            int yy = y - 1 + r;
            bool yok = (yy >= 0 && yy < 256);
#pragma unroll
            for (int c = 0; c < 6; c++) {
                int xx = x0 - 1 + c;
                v[ci][r][c] = (yok && xx >= 0 && xx < 256) ? ch[yy*256 + xx] : 0.f;
            }
        }
    }
    __syncthreads();

    for (int co = 0; co < 50; co++) {
        float a0 = 0.f, a1 = 0.f, a2 = 0.f, a3 = 0.f;
#pragma unroll
        for (int ci = 0; ci < 3; ci++) {
            const float* wp = &ws[(co*3 + ci)*9];
#pragma unroll
            for (int r = 0; r < 3; r++) {
                float w0 = wp[r*3+0], w1 = wp[r*3+1], w2 = wp[r*3+2];
                a0 += w0*v[ci][r][0] + w1*v[ci][r][1] + w2*v[ci][r][2];
                a1 += w0*v[ci][r][1] + w1*v[ci][r][2] + w2*v[ci][r][3];
                a2 += w0*v[ci][r][2] + w1*v[ci][r][3] + w2*v[ci][r][4];
                a3 += w0*v[ci][r][3] + w1*v[ci][r][4] + w2*v[ci][r][5];
            }
        }
        a0 = a0 >= 0.f ? a0 : 0.01f*a0;
        a1 = a1 >= 0.f ? a1 : 0.01f*a1;
        a2 = a2 >= 0.f ? a2 : 0.01f*a2;
        a3 = a3 >= 0.f ? a3 : 0.01f*a3;
        float4 o = make_float4(a0, a1, a2, a3);
        *(float4*)&out[(b*100 + co_base + co)*HWs + y*256 + x0] = o;
    }
}

/* ---------------- conv 100->X (f32x2, 4-slot ring, pair barriers) -------- */
/* block (8,16); thread = 8 x-pixels (4 f32x2 pairs) * NCO chans, 1 row.
   Block covers 64x16 px. 4-slot ring of 18x76 planes processed in ci-PAIRS:
   ONE wait_group 0 + ONE __syncthreads per 2 ci (WAR safety: pair-p fills
   target slots last read in pair p-1; the pair-start barrier covers them).
   Both pair fills share one commit group -> wait_group 0 waits exactly the
   previous pair's fills (issued a full pair earlier).
   Weights chunked CHK ci at a time (pair-aligned: 20 for full, 50 for split).
   NS = ci split factor; grid.z encodes (b, s, co-group).
   EPI 0: leaky -> out (B,100,H,W) at co_base        (NCO=5, NS=1, CHK=20)
   EPI 1: raw partial -> out + ((s*Bb+b)*2+co)*HWs   (NCO=2, NS=2, CHK=50)
   EPI 3: raw partial -> out + (s*Bb+b)*HWs          (NCO=1, NS=2, CHK=50) */
#define TROW 76
#define TPLANE (18*TROW)       /* 1368 floats */

template<int NCO, int EPI, int NS, int CHK>
__global__ __launch_bounds__(128) void k_conv100(
    const float* __restrict__ in, const float* __restrict__ wbase,
    float* __restrict__ out, int cgroups)
{
    __shared__ __align__(16) float tile[4][TPLANE];
    __shared__ __align__(16) float wch[NCO*CHK*20];  /* CHK ci * 10 pairs * 2 */

    int tx = threadIdx.x, ty = threadIdx.y;
    int tid = ty*8 + tx;
    int bz = blockIdx.z;
    int g = bz % cgroups;
    int rest = bz / cgroups;
    int s = rest % NS;
    int b = rest / NS;
    int co_base = g * NCO;

    const int cilen = 100 / NS;
    const int cb = s * cilen;

    int gbx = blockIdx.x*64 - 4;
    int gy0 = blockIdx.y*16 - 1;
    const float* inb = in + b*100*HWs;

    /* load one CHK-ci weight chunk (absolute chunk index ca) */
    auto wfill = [&](int ca) {
        for (int idx = tid; idx < NCO*CHK*9; idx += 128) {
            int co = idx / (CHK*9), rem = idx - co*(CHK*9);
            int cil = rem / 9, tap = rem - cil*9;
            float w = wbase[(co_base + co)*900 + (ca*CHK + cil)*9 + tap];
            int pos = ((co*CHK + cil)*10 + tap)*2;
            wch[pos] = w; wch[pos+1] = w;
        }
    };

    /* async vec16 fill of one ci plane: 18 rows x 18 chunks = 324 */
    auto fill = [&](int slot, int ci) {
        float* dst = &tile[slot][0];
        const float* srcp = inb + ci*HWs;
#pragma unroll
        for (int u = 0; u < 3; u++) {
            int idx = tid + u*128;
            if (idx < 324) {
                int r = idx / 18, c = idx - r*18;
                int gy = gy0 + r;
                int gxs = gbx + 4*c;
                bool ok = (gy >= 0) & (gy < 256) & (gxs >= 0) & (gxs <= 252);
                const float* gp = ok ? (srcp + gy*256 + gxs) : srcp;
                cp_async16(dst + r*TROW + 4*c, gp, ok);
            }
        }
    };

    u64 acc[NCO][4];
#pragma unroll
    for (int co = 0; co < NCO; co++)
#pragma unroll
        for (int j = 0; j < 4; j++) acc[co][j] = 0ull;

    /* compute one ci from (slot, cil-within-chunk) */
    auto compute = [&](int slot, int cil) {
#pragma unroll
        for (int r = 0; r < 3; r++) {
            const float* rp = &tile[slot][(ty + r)*TROW + tx*8];
            u64 eL = *(const u64*)(rp + 2);
            float4 q0 = *(const float4*)(rp + 4);
            float4 q1 = *(const float4*)(rp + 8);
            u64 e4 = *(const u64*)(rp + 12);
            u64 e0 = ((const u64*)&q0)[0], e1 = ((const u64*)&q0)[1];
            u64 e2 = ((const u64*)&q1)[0], e3 = ((const u64*)&q1)[1];
            u64 o0 = funnel(eL, e0);
            u64 o1 = funnel(e0, e1);
            u64 o2 = funnel(e1, e2);
            u64 o3 = funnel(e2, e3);
            u64 o4 = funnel(e3, e4);
#pragma unroll
            for (int co = 0; co < NCO; co++) {
                const u64* wq = (const u64*)&wch[(co*CHK + cil)*20];
                u64 w0, w1, w2;
                if (r == 0) {
                    float4 f = *(const float4*)(wq + 0);
                    w0 = ((const u64*)&f)[0]; w1 = ((const u64*)&f)[1];
                    w2 = wq[2];
                } else if (r == 1) {
                    w0 = wq[3];
                    float4 f = *(const float4*)(wq + 4);
                    w1 = ((const u64*)&f)[0]; w2 = ((const u64*)&f)[1];
                } else {
                    float4 f = *(const float4*)(wq + 6);
                    w0 = ((const u64*)&f)[0]; w1 = ((const u64*)&f)[1];
                    w2 = wq[8];
                }
                ffma2(acc[co][0], w0, o0);
                ffma2(acc[co][1], w0, o1);
                ffma2(acc[co][2], w0, o2);
                ffma2(acc[co][3], w0, o3);
                ffma2(acc[co][0], w1, e0);
                ffma2(acc[co][1], w1, e1);
                ffma2(acc[co][2], w1, e2);
                ffma2(acc[co][3], w1, e3);
                ffma2(acc[co][0], w2, o1);
                ffma2(acc[co][1], w2, o2);
                ffma2(acc[co][2], w2, o3);
                ffma2(acc[co][3], w2, o4);
            }
        }
    };

    /* prologue: planes cb, cb+1 -> slots 0,1 as ONE group */
    fill(0, cb);
    fill(1, cb + 1);
    cp_commit();

    const int npairs = cilen / 2;
    for (int p = 0; p < npairs; p++) {
        int ri0 = 2*p;                 /* relative ci of pair */
        cp_wait0();
        __syncthreads();               /* pair fills visible + WAR cover */

        int cil0 = ri0 % CHK;
        if (cil0 == 0) {
            wfill((cb + ri0) / CHK);
            __syncthreads();
        }

        int s0 = ri0 & 3, s1 = s0 + 1;
        if (ri0 + 2 < cilen) {         /* next pair's fills, one group */
            fill((s0 + 2) & 3, cb + ri0 + 2);
            fill((s1 + 2) & 3, cb + ri0 + 3);
            cp_commit();
        }

        compute(s0, cil0);
        compute(s1, cil0 + 1);
    }

    int x0 = blockIdx.x*64 + tx*8;
    int y  = blockIdx.y*16 + ty;
    int pbase = y*256 + x0;

    float a[NCO][8];
#pragma unroll
    for (int co = 0; co < NCO; co++)
#pragma unroll
        for (int j = 0; j < 4; j++) upk2(acc[co][j], a[co][2*j], a[co][2*j+1]);

    if (EPI == 0) {
#pragma unroll
        for (int co = 0; co < NCO; co++) {
#pragma unroll
            for (int px = 0; px < 8; px++) {
                float v = a[co][px];
                a[co][px] = v >= 0.f ? v : 0.01f*v;
            }
            float* dst = out + (b*100 + co_base + co)*HWs + pbase;
            *(float4*)dst     = make_float4(a[co][0],a[co][1],a[co][2],a[co][3]);
            *(float4*)(dst+4) = make_float4(a[co][4],a[co][5],a[co][6],a[co][7]);
        }
    } else if (EPI == 1) {
#pragma unroll
        for (int co = 0; co < NCO; co++) {
            float* dst = out + ((s*Bb + b)*2 + co)*HWs + pbase;
            *(float4*)dst     = make_float4(a[co][0],a[co][1],a[co][2],a[co][3]);
            *(float4*)(dst+4) = make_float4(a[co][4],a[co][5],a[co][6],a[co][7]);
        }
    } else {
        float* dst = out + (s*Bb + b)*HWs + pbase;
        *(float4*)dst     = make_float4(a[0][0],a[0][1],a[0][2],a[0][3]);
        *(float4*)(dst+4) = make_float4(a[0][4],a[0][5],a[0][6],a[0][7]);
    }
}

/* ---------------- blurs ---------------- */

/* reads summed ci-split partials: in[gid] + in[gid + B2HW] */
__global__ __launch_bounds__(256) void k_blur_h(const float* __restrict__ in,
                                                float* __restrict__ out) {
    __shared__ float srow[306];
    __shared__ float sg[51];
    int tid = threadIdx.x;
    int rb = blockIdx.x * 256;
    srow[25 + tid] = in[rb + tid] + in[rb + tid + B2HW];
    if (tid < 25) { srow[tid] = 0.f; srow[281 + tid] = 0.f; }
    if (tid < 51) sg[tid] = g_gauss[tid];
    __syncthreads();
    float acc = 0.f;
#pragma unroll
    for (int k = 0; k < 51; k++) acc += sg[k] * srow[tid + k];
    out[rb + tid] = acc;
}

__global__ __launch_bounds__(256) void k_blur_v(const float* __restrict__ in,
                                                float* __restrict__ fld) {
    __shared__ float sg[51];
    if (threadIdx.x < 51) sg[threadIdx.x] = g_gauss[threadIdx.x];
    __syncthreads();
    int gid = blockIdx.x * 256 + threadIdx.x;
    int x  = gid & 255;
    int y  = (gid >> 8) & 255;
    int ch = gid >> 16;
    const float* col = in + ch*HWs + x;
    float acc = 0.f;
    for (int k = 0; k < 51; k++) {
        int yy = y + k - 25;
        if (yy >= 0 && yy < 256) acc += sg[k] * col[yy*256];
    }
    fld[gid] = acc;
    g_def[gid] -= acc / 5.0f;
}

/* ---------------- deform / compose ---------------- */

__device__ __forceinline__ float bilin(const float* __restrict__ im, float x, float y) {
    float x0f = floorf(x), y0f = floorf(y);
    float wx = x - x0f, wy = y - y0f;
    int x0 = (int)x0f, y0 = (int)y0f;
    float s = 0.f;
#pragma unroll
    for (int dy = 0; dy < 2; dy++) {
        int yi = y0 + dy;
        if (yi < 0 || yi > 255) continue;
        float wyv = dy ? wy : (1.f - wy);
#pragma unroll
        for (int dx = 0; dx < 2; dx++) {
            int xi = x0 + dx;
            if (xi < 0 || xi > 255) continue;
            float wxv = dx ? wx : (1.f - wx);
            s += im[yi*256 + xi] * (wxv * wyv);
        }
    }
    return s;
}

__global__ void k_deform(const float* __restrict__ in, float* __restrict__ out) {
    int gid = blockIdx.x * blockDim.x + threadIdx.x;
    if (gid >= BHW) return;
    int b = gid / HWs, p = gid % HWs;
    float x = g_def[b*2*HWs + p];
    float y = g_def[b*2*HWs + HWs + p];
    out[gid] = bilin(in + b*HWs, x, y);
}

struct Rd5 { const float* p[5]; int n; };

__global__ void k_compose(const float* __restrict__ src,
                          const float* __restrict__ seg,
                          Rd5 rds, float* __restrict__ outimg) {
    int gid = blockIdx.x * blockDim.x + threadIdx.x;
    if (gid >= BHW) return;
    int b = gid / HWs, p = gid % HWs;
    float x = g_def[b*2*HWs + p];
    float y = g_def[b*2*HWs + HWs + p];
    float s = bilin(src + b*HWs, x, y);
    float m = bilin(seg + b*HWs, x, y);
    float acc = rds.p[0][gid];
    for (int j = 1; j < rds.n; j++) acc += rds.p[j][gid];
    outimg[gid] = s + (acc * (float)(0.02*0.02/5.0)) * m;
}

/* ---------------- launch ---------------- */

extern "C" void kernel_launch(void* const* d_in, const int* in_sizes, int n_in,
                              void* d_out, int out_size) {
    const float* src = (const float*)d_in[0];
    const float* seg = (const float*)d_in[1];
    const float* z0  = (const float*)d_in[2];
    const float* zw1 = (const float*)d_in[3];
    const float* zw2 = (const float*)d_in[4];
    const float* zw3 = (const float*)d_in[5];
    const float* vw1 = (const float*)d_in[6];
    const float* vw2 = (const float*)d_in[7];
    const float* vw3 = (const float*)d_in[8];
    float* out = (float*)d_out;

    float *hA, *hB, *defp, *ft2, *fp, *rp, *rd;
    cudaGetSymbolAddress((void**)&hA,  g_hA);
    cudaGetSymbolAddress((void**)&hB,  g_hB);
    cudaGetSymbolAddress((void**)&defp, g_def);
    cudaGetSymbolAddress((void**)&ft2, g_ft2);
    cudaGetSymbolAddress((void**)&fp,  g_fp);
    cudaGetSymbolAddress((void**)&rp,  g_rp);
    cudaGetSymbolAddress((void**)&rd,  g_rd);

    k_gauss<<<1, 32>>>();
    k_init<<<BHW/256, 256>>>(src, z0, out);

    dim3 blk3(32, 8), grd3(2, 32, Bb*2);
    dim3 blkC(8, 16);

    for (int i = 0; i < 5; i++) {
        /* ---- z path: residual update ---- */
        k_conv_c3<<<grd3, blk3>>>(out + RES_OFF + i*BHW, HWs,
                                  out + IMG_OFF + i*BHW, HWs,
                                  out + IMG_OFF,         HWs,
                                  zw1 + i*2700, hA);
        k_conv100<5,0,1,20><<<dim3(4,16,Bb*20), blkC>>>(hA, zw2 + i*90000, hB, 20);
        /* 100->1 conv split over ci halves -> partials, then combine */
        k_conv100<1,3,2,50><<<dim3(4,16,Bb*2), blkC>>>(hB, zw3 + i*900, rp, 1);
        float* rd_new = rd + (((size_t)(i % 2))*6 + (i + 1))*BHW;
        k_res_combine<<<BHW/256, 256>>>(out + RES_OFF + i*BHW, rp,
                                        out + RES_OFF + (i+1)*BHW, rd_new);
        /* ---- re-deform previous residuals with PRE-update deformation ---- */
        for (int j = 1; j <= i; j++) {
            const float* s_ = rd + (((size_t)((i+1) % 2))*6 + j)*BHW;
            float*       d_ = rd + (((size_t)(i % 2))*6 + j)*BHW;
            k_deform<<<BHW/256, 256>>>(s_, d_);
        }
        /* ---- v path: velocity field ---- */
        k_conv_c3<<<grd3, blk3>>>(defp,       2*HWs,
                                  defp + HWs, 2*HWs,
                                  out + IMG_OFF + i*BHW, HWs,
                                  vw1 + i*2700, hA);
        k_conv100<5,0,1,20><<<dim3(4,16,Bb*20), blkC>>>(hA, vw2 + i*90000, hB, 20);
        /* 100->2 conv split over ci halves -> partials; blur_h sums them */
        k_conv100<2,1,2,50><<<dim3(4,16,Bb*2), blkC>>>(hB, vw3 + i*1800, fp, 1);
        k_blur_h<<<Bb*2*Hh, 256>>>(fp, ft2);
        k_blur_v<<<B2HW/256, 256>>>(ft2, out + FLD_OFF + i*B2HW);  /* also updates g_def */

        /* ---- compose new image with POST-update deformation ---- */
        Rd5 rds;
        rds.n = i + 1;
        for (int j = 0; j < 5; j++) {
            int slot = (j <= i) ? (j + 1) : 1;
            rds.p[j] = rd + (((size_t)(i % 2))*6 + slot)*BHW;
        }
        k_compose<<<BHW/256, 256>>>(out + IMG_OFF, seg, rds,
                                    out + IMG_OFF + (i+1)*BHW);
        k_grad<<<BHW/256, 256>>>(out + IMG_OFF + (i+1)*BHW,
                                 out + GRD_OFF + (i+1)*B2HW);
    }
}